// round 1
// baseline (speedup 1.0000x reference)
#include <cuda_runtime.h>

#define N_NODES 50000
#define N_EDGES 200000
#define C 32
#define ND 75
#define ED 12
#define NL 3
#define NG 500
#define HID 5
#define BN_EPS 1e-5f

// Scratch (no allocations allowed)
__device__ __align__(16) float g_h[N_NODES * C];
__device__ __align__(16) float g_agg[N_NODES * C];
__device__ float g_stats[2 * C];

// ---- packed fp32x2 helpers (sm_103a) ----
__device__ __forceinline__ void fma2(unsigned long long& acc, unsigned long long a,
                                     unsigned long long b) {
    asm("fma.rn.f32x2 %0, %1, %2, %0;" : "+l"(acc) : "l"(a), "l"(b));
}
__device__ __forceinline__ unsigned long long pack2(float v) {
    unsigned long long r;
    asm("mov.b64 %0, {%1, %1};" : "=l"(r) : "f"(v));
    return r;
}

// ---------------------------------------------------------------------------
// h = leaky(x @ lin_W + lin_b)
// ---------------------------------------------------------------------------
__global__ void __launch_bounds__(256) k_init(const float* __restrict__ x,
                                              const float* __restrict__ W,
                                              const float* __restrict__ b) {
    __shared__ __align__(16) float sW[ND * C];
    __shared__ float sb[C];
    for (int i = threadIdx.x; i < ND * C; i += blockDim.x) sW[i] = W[i];
    if (threadIdx.x < C) sb[threadIdx.x] = b[threadIdx.x];
    __syncthreads();
    int n = blockIdx.x * blockDim.x + threadIdx.x;
    if (n >= N_NODES) return;
    float acc[C];
#pragma unroll
    for (int d = 0; d < C; d++) acc[d] = sb[d];
    const float* xr = x + n * ND;
#pragma unroll 5
    for (int j = 0; j < ND; j++) {
        float xv = __ldg(xr + j);
#pragma unroll
        for (int d = 0; d < C; d++) acc[d] += xv * sW[j * C + d];
    }
    float4* ho = (float4*)(g_h + n * C);
#pragma unroll
    for (int q = 0; q < 8; q++) {
        float4 v;
        float a0 = acc[4 * q], a1 = acc[4 * q + 1], a2 = acc[4 * q + 2], a3 = acc[4 * q + 3];
        v.x = a0 > 0.f ? a0 : 0.01f * a0;
        v.y = a1 > 0.f ? a1 : 0.01f * a1;
        v.z = a2 > 0.f ? a2 : 0.01f * a2;
        v.w = a3 > 0.f ? a3 : 0.01f * a3;
        ho[q] = v;
    }
}

// ---------------------------------------------------------------------------
// agg = h @ root_W + conv_b    (also zeroes the BN stats accumulators)
// ---------------------------------------------------------------------------
__global__ void __launch_bounds__(256) k_root(const float* __restrict__ rW,
                                              const float* __restrict__ cb) {
    __shared__ __align__(16) float sW[C * C];
    __shared__ float sb[C];
    for (int i = threadIdx.x; i < C * C; i += blockDim.x) sW[i] = rW[i];
    if (threadIdx.x < C) sb[threadIdx.x] = cb[threadIdx.x];
    if (blockIdx.x == 0 && threadIdx.x < 2 * C) g_stats[threadIdx.x] = 0.f;
    __syncthreads();
    int n = blockIdx.x * blockDim.x + threadIdx.x;
    if (n >= N_NODES) return;
    float hr[C];
    const float4* hrp = (const float4*)(g_h + n * C);
#pragma unroll
    for (int q = 0; q < 8; q++) {
        float4 v = hrp[q];
        hr[4 * q] = v.x; hr[4 * q + 1] = v.y; hr[4 * q + 2] = v.z; hr[4 * q + 3] = v.w;
    }
    float acc[C];
#pragma unroll
    for (int d = 0; d < C; d++) acc[d] = sb[d];
#pragma unroll 8
    for (int c = 0; c < C; c++) {
        float hv = hr[c];
#pragma unroll
        for (int d = 0; d < C; d++) acc[d] += hv * sW[c * C + d];
    }
    float4* ao = (float4*)(g_agg + n * C);
#pragma unroll
    for (int q = 0; q < 8; q++) {
        float4 v;
        v.x = acc[4 * q]; v.y = acc[4 * q + 1]; v.z = acc[4 * q + 2]; v.w = acc[4 * q + 3];
        ao[q] = v;
    }
}

// ---------------------------------------------------------------------------
// Edge kernel: fused edge-MLP + per-edge matvec + scatter-add.
//   msg[d] = sum_{k=0..5} coef[k] * sum_c h_src[c] * sW[k][c][d]
//   (k<5: coef=relu(edge MLP hidden), weights=mes_W2; k=5: coef=1, weights=mes_b2)
// Thread-per-edge; weights broadcast from SMEM; packed f32x2 FMAs.
// ---------------------------------------------------------------------------
__global__ void __launch_bounds__(256) k_edge(const float* __restrict__ ea,
                                              const int* __restrict__ src,
                                              const int* __restrict__ dst,
                                              const float* __restrict__ W1,
                                              const float* __restrict__ b1,
                                              const float* __restrict__ W2,
                                              const float* __restrict__ b2) {
    __shared__ __align__(16) float sW[6 * C * C];  // 24 KB
    __shared__ float sW1[ED * HID];
    __shared__ float sb1[HID];
    for (int i = threadIdx.x; i < HID * C * C; i += blockDim.x) sW[i] = W2[i];
    for (int i = threadIdx.x; i < C * C; i += blockDim.x) sW[HID * C * C + i] = b2[i];
    if (threadIdx.x < ED * HID) sW1[threadIdx.x] = W1[threadIdx.x];
    if (threadIdx.x < HID) sb1[threadIdx.x] = b1[threadIdx.x];
    __syncthreads();

    int e = blockIdx.x * blockDim.x + threadIdx.x;
    if (e >= N_EDGES) return;

    // edge MLP hidden layer (relu)
    float eav[ED];
    const float4* ear = (const float4*)(ea + e * ED);  // 48B rows: 16B aligned
#pragma unroll
    for (int q = 0; q < 3; q++) {
        float4 v = ear[q];
        eav[4 * q] = v.x; eav[4 * q + 1] = v.y; eav[4 * q + 2] = v.z; eav[4 * q + 3] = v.w;
    }
    float coef[6];
#pragma unroll
    for (int k = 0; k < HID; k++) {
        float s = sb1[k];
#pragma unroll
        for (int j = 0; j < ED; j++) s += eav[j] * sW1[j * HID + k];
        coef[k] = fmaxf(s, 0.f);
    }
    coef[5] = 1.f;

    // gather source features
    int sn = src[e];
    float hs[C];
    const float4* hrp = (const float4*)(g_h + sn * C);
#pragma unroll
    for (int q = 0; q < 8; q++) {
        float4 v = hrp[q];
        hs[4 * q] = v.x; hs[4 * q + 1] = v.y; hs[4 * q + 2] = v.z; hs[4 * q + 3] = v.w;
    }

    // main contraction: 16 packed accumulators = 32 outputs
    unsigned long long acc[16];
#pragma unroll
    for (int j = 0; j < 16; j++) acc[j] = 0ULL;

#pragma unroll 4
    for (int c = 0; c < C; c++) {
        float hc = hs[c];
#pragma unroll
        for (int k = 0; k < 6; k++) {
            unsigned long long p2 = pack2(coef[k] * hc);
            const ulonglong2* wr = (const ulonglong2*)(sW + k * C * C + c * C);
#pragma unroll
            for (int j = 0; j < 8; j++) {
                ulonglong2 w = wr[j];
                fma2(acc[2 * j], p2, w.x);
                fma2(acc[2 * j + 1], p2, w.y);
            }
        }
    }

    // scatter-add to destination node
    int dn = dst[e];
    float* ag = g_agg + dn * C;
#pragma unroll
    for (int j = 0; j < 16; j++) {
        float2 v = *(float2*)&acc[j];
        atomicAdd(ag + 2 * j, v.x);
        atomicAdd(ag + 2 * j + 1, v.y);
    }
}

// ---------------------------------------------------------------------------
// BN statistics: per-channel sum and sum of squares
// ---------------------------------------------------------------------------
__global__ void __launch_bounds__(256) k_stats() {
    __shared__ float ssum[C], ssq[C];
    if (threadIdx.x < C) { ssum[threadIdx.x] = 0.f; ssq[threadIdx.x] = 0.f; }
    __syncthreads();
    int stride = gridDim.x * blockDim.x;  // multiple of 32
    int c = threadIdx.x & (C - 1);
    float ls = 0.f, lq = 0.f;
    for (int i = blockIdx.x * blockDim.x + threadIdx.x; i < N_NODES * C; i += stride) {
        float v = g_agg[i];
        ls += v;
        lq += v * v;
    }
    atomicAdd(&ssum[c], ls);
    atomicAdd(&ssq[c], lq);
    __syncthreads();
    if (threadIdx.x < C) {
        atomicAdd(&g_stats[threadIdx.x], ssum[threadIdx.x]);
        atomicAdd(&g_stats[C + threadIdx.x], ssq[threadIdx.x]);
    }
}

// ---------------------------------------------------------------------------
// BN normalize (+ optional leaky), writes h for next layer
// ---------------------------------------------------------------------------
__global__ void __launch_bounds__(256) k_norm(const float* __restrict__ bg,
                                              const float* __restrict__ bb,
                                              int do_leaky) {
    __shared__ float smu[C], srs[C], sg[C], sb[C];
    if (threadIdx.x < C) {
        float mu = g_stats[threadIdx.x] * (1.0f / N_NODES);
        float var = g_stats[C + threadIdx.x] * (1.0f / N_NODES) - mu * mu;
        smu[threadIdx.x] = mu;
        srs[threadIdx.x] = rsqrtf(var + BN_EPS);
        sg[threadIdx.x] = bg[threadIdx.x];
        sb[threadIdx.x] = bb[threadIdx.x];
    }
    __syncthreads();
    int stride = gridDim.x * blockDim.x;
    for (int i = blockIdx.x * blockDim.x + threadIdx.x; i < N_NODES * C; i += stride) {
        int c = i & (C - 1);
        float v = (g_agg[i] - smu[c]) * srs[c] * sg[c] + sb[c];
        if (do_leaky) v = v > 0.f ? v : 0.01f * v;
        g_h[i] = v;
    }
}

// ---------------------------------------------------------------------------
// Readout: out[g] = pred_b + sum_{n in g} h[n] . pred_W
// ---------------------------------------------------------------------------
__global__ void k_out_init(const float* __restrict__ pb, float* out) {
    int g = blockIdx.x * blockDim.x + threadIdx.x;
    if (g < NG) out[g] = pb[0];
}

__global__ void __launch_bounds__(256) k_readout(const int* __restrict__ batch,
                                                 const float* __restrict__ pW,
                                                 float* out) {
    __shared__ float spw[C];
    if (threadIdx.x < C) spw[threadIdx.x] = pW[threadIdx.x];
    __syncthreads();
    int n = blockIdx.x * blockDim.x + threadIdx.x;
    if (n >= N_NODES) return;
    float s = 0.f;
    const float4* hrp = (const float4*)(g_h + n * C);
#pragma unroll
    for (int q = 0; q < 8; q++) {
        float4 v = hrp[q];
        s += v.x * spw[4 * q] + v.y * spw[4 * q + 1] + v.z * spw[4 * q + 2] +
             v.w * spw[4 * q + 3];
    }
    atomicAdd(&out[batch[n]], s);
}

// ---------------------------------------------------------------------------
extern "C" void kernel_launch(void* const* d_in, const int* in_sizes, int n_in,
                              void* d_out, int out_size) {
    const float* x       = (const float*)d_in[0];
    const int*   ei      = (const int*)d_in[1];
    const float* ea      = (const float*)d_in[2];
    const int*   batch   = (const int*)d_in[3];
    const float* lin_W   = (const float*)d_in[4];
    const float* lin_b   = (const float*)d_in[5];
    const float* mes_W1  = (const float*)d_in[6];
    const float* mes_b1  = (const float*)d_in[7];
    const float* mes_W2  = (const float*)d_in[8];
    const float* mes_b2  = (const float*)d_in[9];
    const float* root_W  = (const float*)d_in[10];
    const float* conv_b  = (const float*)d_in[11];
    const float* bn_g    = (const float*)d_in[12];
    const float* bn_b    = (const float*)d_in[13];
    const float* pred_W  = (const float*)d_in[14];
    const float* pred_b  = (const float*)d_in[15];
    float* out = (float*)d_out;

    const int* src = ei;
    const int* dst = ei + N_EDGES;

    k_init<<<(N_NODES + 255) / 256, 256>>>(x, lin_W, lin_b);
    for (int l = 0; l < NL; l++) {
        k_root<<<(N_NODES + 255) / 256, 256>>>(root_W + l * C * C, conv_b + l * C);
        k_edge<<<(N_EDGES + 255) / 256, 256>>>(ea, src, dst,
                                               mes_W1 + l * ED * HID, mes_b1 + l * HID,
                                               mes_W2 + l * HID * C * C, mes_b2 + l * C * C);
        k_stats<<<592, 256>>>();
        k_norm<<<592, 256>>>(bn_g + l * C, bn_b + l * C, (l < NL - 1) ? 1 : 0);
    }
    k_out_init<<<2, 256>>>(pred_b, out);
    k_readout<<<(N_NODES + 255) / 256, 256>>>(batch, pred_W, out);
}

// round 2
// speedup vs baseline: 1.3217x; 1.3217x over previous
#include <cuda_runtime.h>

#define N_NODES 50000
#define N_EDGES 200000
#define C 32
#define ND 75
#define ED 12
#define NL 3
#define NG 500
#define HID 5
#define BN_EPS 1e-5f

// Scratch (no allocations allowed)
__device__ __align__(16) float g_h[N_NODES * C];          // layer-0 input features
__device__ __align__(16) float g_agg[N_NODES * C];        // conv accumulator
__device__ __align__(16) float g_v[N_NODES * 6 * C];      // v[n,k,d] = sum_c h[n,c] W2[k,c,d]
__device__ float g_stats[2 * C];                          // BN sum / sumsq

// ---- packed fp32x2 helpers (sm_103a) ----
__device__ __forceinline__ void fma2(unsigned long long& acc, unsigned long long a,
                                     unsigned long long b) {
    asm("fma.rn.f32x2 %0, %1, %2, %0;" : "+l"(acc) : "l"(a), "l"(b));
}
__device__ __forceinline__ unsigned long long pack2(float v) {
    unsigned long long r;
    asm("mov.b64 %0, {%1, %1};" : "=l"(r) : "f"(v));
    return r;
}
__device__ __forceinline__ void red_add_v4(float* addr, float4 v) {
    asm volatile("red.global.add.v4.f32 [%0], {%1, %2, %3, %4};"
                 :: "l"(addr), "f"(v.x), "f"(v.y), "f"(v.z), "f"(v.w) : "memory");
}

// ---------------------------------------------------------------------------
// h = leaky(x @ lin_W + lin_b)
// ---------------------------------------------------------------------------
__global__ void __launch_bounds__(256) k_init(const float* __restrict__ x,
                                              const float* __restrict__ W,
                                              const float* __restrict__ b) {
    __shared__ __align__(16) float sW[ND * C];
    __shared__ float sb[C];
    for (int i = threadIdx.x; i < ND * C; i += blockDim.x) sW[i] = W[i];
    if (threadIdx.x < C) sb[threadIdx.x] = b[threadIdx.x];
    __syncthreads();
    int n = blockIdx.x * blockDim.x + threadIdx.x;
    if (n >= N_NODES) return;
    float acc[C];
#pragma unroll
    for (int d = 0; d < C; d++) acc[d] = sb[d];
    const float* xr = x + n * ND;
#pragma unroll 5
    for (int j = 0; j < ND; j++) {
        float xv = __ldg(xr + j);
#pragma unroll
        for (int d = 0; d < C; d++) acc[d] += xv * sW[j * C + d];
    }
    float4* ho = (float4*)(g_h + n * C);
#pragma unroll
    for (int q = 0; q < 8; q++) {
        float4 v;
        float a0 = acc[4 * q], a1 = acc[4 * q + 1], a2 = acc[4 * q + 2], a3 = acc[4 * q + 3];
        v.x = a0 > 0.f ? a0 : 0.01f * a0;
        v.y = a1 > 0.f ? a1 : 0.01f * a1;
        v.z = a2 > 0.f ? a2 : 0.01f * a2;
        v.w = a3 > 0.f ? a3 : 0.01f * a3;
        ho[q] = v;
    }
}

// ---------------------------------------------------------------------------
// k_v: per-node precompute. Warp = (slot, 32 nodes). Slots:
//   0..4 : v[n,k,:] = h[n,:] @ W2[k]      (-> g_v)
//   5    : v[n,5,:] = h[n,:] @ b2         (-> g_v)
//   6    : agg[n,:] = h[n,:] @ rootW + cb (-> g_agg)
// For layers >0, h is computed inline: BN(prev stats) + leaky on g_agg.
// ---------------------------------------------------------------------------
__global__ void __launch_bounds__(256) k_v(const float* __restrict__ W2,
                                           const float* __restrict__ b2,
                                           const float* __restrict__ rootW,
                                           const float* __restrict__ cb,
                                           const float* __restrict__ bng,
                                           const float* __restrict__ bnb,
                                           int first) {
    __shared__ __align__(16) float sW[7 * C * C];   // 28 KB
    __shared__ float snorm[4 * C];                  // mu, rs, gamma, beta
    __shared__ float scb[C];
    for (int i = threadIdx.x; i < HID * C * C; i += blockDim.x) sW[i] = W2[i];
    for (int i = threadIdx.x; i < C * C; i += blockDim.x) {
        sW[5 * C * C + i] = b2[i];
        sW[6 * C * C + i] = rootW[i];
    }
    if (threadIdx.x < C) {
        scb[threadIdx.x] = cb[threadIdx.x];
        if (!first) {
            float mu = g_stats[threadIdx.x] * (1.0f / N_NODES);
            float var = g_stats[C + threadIdx.x] * (1.0f / N_NODES) - mu * mu;
            snorm[threadIdx.x] = mu;
            snorm[C + threadIdx.x] = rsqrtf(var + BN_EPS);
            snorm[2 * C + threadIdx.x] = bng[threadIdx.x];
            snorm[3 * C + threadIdx.x] = bnb[threadIdx.x];
        }
    }
    __syncthreads();

    int gw = blockIdx.x * 8 + (threadIdx.x >> 5);
    int slot = gw % 7;
    int node = (gw / 7) * 32 + (threadIdx.x & 31);
    if (node >= N_NODES) return;

    // load h (normalize inline for layers > 0)
    float h[C];
    if (first) {
        const float4* hp = (const float4*)(g_h + node * C);
#pragma unroll
        for (int q = 0; q < 8; q++) {
            float4 v = hp[q];
            h[4 * q] = v.x; h[4 * q + 1] = v.y; h[4 * q + 2] = v.z; h[4 * q + 3] = v.w;
        }
    } else {
        const float4* ap = (const float4*)(g_agg + node * C);
#pragma unroll
        for (int q = 0; q < 8; q++) {
            float4 v = ap[q];
            float t[4] = {v.x, v.y, v.z, v.w};
#pragma unroll
            for (int r = 0; r < 4; r++) {
                int c = 4 * q + r;
                float val = (t[r] - snorm[c]) * snorm[C + c] * snorm[2 * C + c] + snorm[3 * C + c];
                h[c] = val > 0.f ? val : 0.01f * val;   // leaky (layers 0,1 outputs always leaky'd)
            }
        }
    }

    // contraction: 32 outputs in 16 packed accumulators
    unsigned long long acc[16];
#pragma unroll
    for (int j = 0; j < 16; j++) acc[j] = 0ULL;
    const float* wbase = sW + slot * C * C;
#pragma unroll 8
    for (int c = 0; c < C; c++) {
        unsigned long long p = pack2(h[c]);
        const ulonglong2* wr = (const ulonglong2*)(wbase + c * C);
#pragma unroll
        for (int j = 0; j < 8; j++) {
            ulonglong2 w = wr[j];
            fma2(acc[2 * j], p, w.x);
            fma2(acc[2 * j + 1], p, w.y);
        }
    }

    if (slot == 6) {
        float4* ao = (float4*)(g_agg + node * C);
        const float* af = (const float*)acc;
#pragma unroll
        for (int q = 0; q < 8; q++) {
            float4 v;
            v.x = af[4 * q] + scb[4 * q];
            v.y = af[4 * q + 1] + scb[4 * q + 1];
            v.z = af[4 * q + 2] + scb[4 * q + 2];
            v.w = af[4 * q + 3] + scb[4 * q + 3];
            ao[q] = v;
        }
    } else {
        float4* vo = (float4*)(g_v + node * (6 * C) + slot * C);
        const float4* af = (const float4*)acc;
#pragma unroll
        for (int q = 0; q < 8; q++) vo[q] = af[q];
    }
}

// ---------------------------------------------------------------------------
// Edge kernel: coef = relu(ea@W1+b1) (+1 for bias slot); msg = sum_k coef[k]*v[src,k,:];
// scatter-add to g_agg[dst]. Skips k with coef==0 (ReLU kills ~half).
// Block 0 also zeroes g_stats for this layer's upcoming k_stats.
// ---------------------------------------------------------------------------
__global__ void __launch_bounds__(256) k_edge(const float* __restrict__ ea,
                                              const int* __restrict__ src,
                                              const int* __restrict__ dst,
                                              const float* __restrict__ W1,
                                              const float* __restrict__ b1) {
    __shared__ float sW1[ED * HID];
    __shared__ float sb1[HID];
    if (threadIdx.x < ED * HID) sW1[threadIdx.x] = W1[threadIdx.x];
    if (threadIdx.x < HID) sb1[threadIdx.x] = b1[threadIdx.x];
    if (blockIdx.x == 0 && threadIdx.x < 2 * C) g_stats[threadIdx.x] = 0.f;
    __syncthreads();

    int e = blockIdx.x * blockDim.x + threadIdx.x;
    if (e >= N_EDGES) return;

    float eav[ED];
    const float4* ear = (const float4*)(ea + e * ED);
#pragma unroll
    for (int q = 0; q < 3; q++) {
        float4 v = ear[q];
        eav[4 * q] = v.x; eav[4 * q + 1] = v.y; eav[4 * q + 2] = v.z; eav[4 * q + 3] = v.w;
    }
    float coef[6];
#pragma unroll
    for (int k = 0; k < HID; k++) {
        float s = sb1[k];
#pragma unroll
        for (int j = 0; j < ED; j++) s += eav[j] * sW1[j * HID + k];
        coef[k] = fmaxf(s, 0.f);
    }
    coef[5] = 1.f;

    int sn = src[e];
    const float* vb = g_v + sn * (6 * C);

    unsigned long long acc[16];
#pragma unroll
    for (int j = 0; j < 16; j++) acc[j] = 0ULL;

#pragma unroll
    for (int k = 0; k < 6; k++) {
        float ck = coef[k];
        if (ck == 0.f) continue;   // predicated skip: saves gather + fma
        unsigned long long p = pack2(ck);
        const ulonglong2* vr = (const ulonglong2*)(vb + k * C);
#pragma unroll
        for (int j = 0; j < 8; j++) {
            ulonglong2 w = __ldg((const ulonglong2*)(vr + j));
            fma2(acc[2 * j], p, w.x);
            fma2(acc[2 * j + 1], p, w.y);
        }
    }

    int dn = dst[e];
    float* ag = g_agg + dn * C;
    const float4* af = (const float4*)acc;
#pragma unroll
    for (int q = 0; q < 8; q++) red_add_v4(ag + 4 * q, af[q]);
}

// ---------------------------------------------------------------------------
// BN statistics: per-channel sum / sumsq over g_agg. float4 + shfl + smem stage.
// ---------------------------------------------------------------------------
__global__ void __launch_bounds__(256) k_stats() {
    __shared__ float ss[2 * C];
    if (threadIdx.x < 2 * C) ss[threadIdx.x] = 0.f;
    __syncthreads();
    const float4* A = (const float4*)g_agg;
    float4 s = {0.f, 0.f, 0.f, 0.f}, q = {0.f, 0.f, 0.f, 0.f};
    int stride = gridDim.x * blockDim.x;   // multiple of 8
    for (int i = blockIdx.x * blockDim.x + threadIdx.x; i < N_NODES * 8; i += stride) {
        float4 v = A[i];
        s.x += v.x; s.y += v.y; s.z += v.z; s.w += v.w;
        q.x += v.x * v.x; q.y += v.y * v.y; q.z += v.z * v.z; q.w += v.w * v.w;
    }
    // reduce lanes sharing the same channel group (tid & 7): xor 8, xor 16
#pragma unroll
    for (int off = 8; off <= 16; off <<= 1) {
        s.x += __shfl_xor_sync(0xffffffffu, s.x, off);
        s.y += __shfl_xor_sync(0xffffffffu, s.y, off);
        s.z += __shfl_xor_sync(0xffffffffu, s.z, off);
        s.w += __shfl_xor_sync(0xffffffffu, s.w, off);
        q.x += __shfl_xor_sync(0xffffffffu, q.x, off);
        q.y += __shfl_xor_sync(0xffffffffu, q.y, off);
        q.z += __shfl_xor_sync(0xffffffffu, q.z, off);
        q.w += __shfl_xor_sync(0xffffffffu, q.w, off);
    }
    int lane = threadIdx.x & 31;
    if (lane < 8) {
        int cg = lane * 4;
        atomicAdd(&ss[cg + 0], s.x); atomicAdd(&ss[cg + 1], s.y);
        atomicAdd(&ss[cg + 2], s.z); atomicAdd(&ss[cg + 3], s.w);
        atomicAdd(&ss[C + cg + 0], q.x); atomicAdd(&ss[C + cg + 1], q.y);
        atomicAdd(&ss[C + cg + 2], q.z); atomicAdd(&ss[C + cg + 3], q.w);
    }
    __syncthreads();
    if (threadIdx.x < 2 * C) atomicAdd(&g_stats[threadIdx.x], ss[threadIdx.x]);
}

// ---------------------------------------------------------------------------
// Final: BN (no leaky) + prediction dot + scatter to graphs
// ---------------------------------------------------------------------------
__global__ void k_out_init(const float* __restrict__ pb, float* out) {
    int g = blockIdx.x * blockDim.x + threadIdx.x;
    if (g < NG) out[g] = pb[0];
}

__global__ void __launch_bounds__(256) k_fin(const int* __restrict__ batch,
                                             const float* __restrict__ pW,
                                             const float* __restrict__ bng,
                                             const float* __restrict__ bnb,
                                             float* out) {
    __shared__ float snorm[4 * C];
    __shared__ float spw[C];
    if (threadIdx.x < C) {
        float mu = g_stats[threadIdx.x] * (1.0f / N_NODES);
        float var = g_stats[C + threadIdx.x] * (1.0f / N_NODES) - mu * mu;
        snorm[threadIdx.x] = mu;
        snorm[C + threadIdx.x] = rsqrtf(var + BN_EPS);
        snorm[2 * C + threadIdx.x] = bng[threadIdx.x];
        snorm[3 * C + threadIdx.x] = bnb[threadIdx.x];
        spw[threadIdx.x] = pW[threadIdx.x];
    }
    __syncthreads();
    int n = blockIdx.x * blockDim.x + threadIdx.x;
    if (n >= N_NODES) return;
    const float4* ap = (const float4*)(g_agg + n * C);
    float s = 0.f;
#pragma unroll
    for (int q = 0; q < 8; q++) {
        float4 v = ap[q];
        float t[4] = {v.x, v.y, v.z, v.w};
#pragma unroll
        for (int r = 0; r < 4; r++) {
            int c = 4 * q + r;
            float val = (t[r] - snorm[c]) * snorm[C + c] * snorm[2 * C + c] + snorm[3 * C + c];
            s += val * spw[c];
        }
    }
    atomicAdd(&out[batch[n]], s);
}

// ---------------------------------------------------------------------------
extern "C" void kernel_launch(void* const* d_in, const int* in_sizes, int n_in,
                              void* d_out, int out_size) {
    const float* x       = (const float*)d_in[0];
    const int*   ei      = (const int*)d_in[1];
    const float* ea      = (const float*)d_in[2];
    const int*   batch   = (const int*)d_in[3];
    const float* lin_W   = (const float*)d_in[4];
    const float* lin_b   = (const float*)d_in[5];
    const float* mes_W1  = (const float*)d_in[6];
    const float* mes_b1  = (const float*)d_in[7];
    const float* mes_W2  = (const float*)d_in[8];
    const float* mes_b2  = (const float*)d_in[9];
    const float* root_W  = (const float*)d_in[10];
    const float* conv_b  = (const float*)d_in[11];
    const float* bn_g    = (const float*)d_in[12];
    const float* bn_b    = (const float*)d_in[13];
    const float* pred_W  = (const float*)d_in[14];
    const float* pred_b  = (const float*)d_in[15];
    float* out = (float*)d_out;

    const int* src = ei;
    const int* dst = ei + N_EDGES;

    int vwarps = 7 * ((N_NODES + 31) / 32);
    int vblocks = (vwarps + 7) / 8;

    k_init<<<(N_NODES + 255) / 256, 256>>>(x, lin_W, lin_b);
    for (int l = 0; l < NL; l++) {
        k_v<<<vblocks, 256>>>(mes_W2 + l * HID * C * C, mes_b2 + l * C * C,
                              root_W + l * C * C, conv_b + l * C,
                              l > 0 ? bn_g + (l - 1) * C : bn_g,
                              l > 0 ? bn_b + (l - 1) * C : bn_b,
                              l == 0 ? 1 : 0);
        k_edge<<<(N_EDGES + 255) / 256, 256>>>(ea, src, dst,
                                               mes_W1 + l * ED * HID, mes_b1 + l * HID);
        k_stats<<<296, 256>>>();
    }
    k_out_init<<<2, 256>>>(pred_b, out);
    k_fin<<<(N_NODES + 255) / 256, 256>>>(batch, pred_W, bn_g + 2 * C, bn_b + 2 * C, out);
}

// round 6
// speedup vs baseline: 1.9203x; 1.4529x over previous
#include <cuda_runtime.h>

#define N_NODES 50000
#define N_EDGES 200000
#define C 32
#define ND 75
#define ED 12
#define NL 3
#define NG 500
#define HID 5
#define BN_EPS 1e-5f

// Scratch (no allocations allowed)
__device__ __align__(128) float g_h[N_NODES * C];        // layer-0 input features
__device__ __align__(128) float g_agg[N_NODES * C];      // conv accumulator
__device__ __align__(128) float g_v[N_NODES * 6 * C];    // v[n,k,d] = sum_c h[n,c] W2[k,c,d]
__device__ __align__(128) float g_coef[NL * N_EDGES * 8];// relu(ea@W1+b1), slot5=1, padded
__device__ float g_stats[2 * C];                         // BN sum / sumsq

// ---- packed fp32x2 helpers (sm_103a) ----
__device__ __forceinline__ void fma2(unsigned long long& acc, unsigned long long a,
                                     unsigned long long b) {
    asm("fma.rn.f32x2 %0, %1, %2, %0;" : "+l"(acc) : "l"(a), "l"(b));
}
__device__ __forceinline__ unsigned long long pack2(float v) {
    unsigned long long r;
    asm("mov.b64 %0, {%1, %1};" : "=l"(r) : "f"(v));
    return r;
}
__device__ __forceinline__ void red_add_v4(float* addr, float4 v) {
    asm volatile("red.global.add.v4.f32 [%0], {%1, %2, %3, %4};"
                 :: "l"(addr), "f"(v.x), "f"(v.y), "f"(v.z), "f"(v.w) : "memory");
}

// ---------------------------------------------------------------------------
// h = leaky(x @ lin_W + lin_b)
// ---------------------------------------------------------------------------
__global__ void __launch_bounds__(256) k_init(const float* __restrict__ x,
                                              const float* __restrict__ W,
                                              const float* __restrict__ b) {
    __shared__ __align__(16) float sW[ND * C];
    __shared__ float sb[C];
    for (int i = threadIdx.x; i < ND * C; i += blockDim.x) sW[i] = W[i];
    if (threadIdx.x < C) sb[threadIdx.x] = b[threadIdx.x];
    __syncthreads();
    int n = blockIdx.x * blockDim.x + threadIdx.x;
    if (n >= N_NODES) return;
    float acc[C];
#pragma unroll
    for (int d = 0; d < C; d++) acc[d] = sb[d];
    const float* xr = x + n * ND;
#pragma unroll 5
    for (int j = 0; j < ND; j++) {
        float xv = __ldg(xr + j);
#pragma unroll
        for (int d = 0; d < C; d++) acc[d] += xv * sW[j * C + d];
    }
    float4* ho = (float4*)(g_h + n * C);
#pragma unroll
    for (int q = 0; q < 8; q++) {
        float4 v;
        float a0 = acc[4 * q], a1 = acc[4 * q + 1], a2 = acc[4 * q + 2], a3 = acc[4 * q + 3];
        v.x = a0 > 0.f ? a0 : 0.01f * a0;
        v.y = a1 > 0.f ? a1 : 0.01f * a1;
        v.z = a2 > 0.f ? a2 : 0.01f * a2;
        v.w = a3 > 0.f ? a3 : 0.01f * a3;
        ho[q] = v;
    }
}

// ---------------------------------------------------------------------------
// Precompute edge-MLP coefs for ALL layers (edge_attr is layer-invariant).
// g_coef[(l*E + e)*8 + k] = relu(ea[e] @ W1[l] + b1[l])[k] for k<5; [5]=1.
// ---------------------------------------------------------------------------
__global__ void __launch_bounds__(256) k_coef(const float* __restrict__ ea,
                                              const float* __restrict__ W1,
                                              const float* __restrict__ b1) {
    __shared__ float sW1[NL * ED * HID];   // 180
    __shared__ float sb1[NL * HID];        // 15
    if (threadIdx.x < NL * ED * HID) sW1[threadIdx.x] = W1[threadIdx.x];
    if (threadIdx.x < NL * HID) sb1[threadIdx.x] = b1[threadIdx.x];
    __syncthreads();
    int e = blockIdx.x * blockDim.x + threadIdx.x;
    if (e >= N_EDGES) return;
    float eav[ED];
    const float4* ear = (const float4*)(ea + e * ED);
#pragma unroll
    for (int q = 0; q < 3; q++) {
        float4 v = ear[q];
        eav[4 * q] = v.x; eav[4 * q + 1] = v.y; eav[4 * q + 2] = v.z; eav[4 * q + 3] = v.w;
    }
#pragma unroll
    for (int l = 0; l < NL; l++) {
        float out[8];
#pragma unroll
        for (int k = 0; k < HID; k++) {
            float s = sb1[l * HID + k];
#pragma unroll
            for (int j = 0; j < ED; j++) s += eav[j] * sW1[(l * ED + j) * HID + k];
            out[k] = fmaxf(s, 0.f);
        }
        out[5] = 1.f; out[6] = 0.f; out[7] = 0.f;
        float4* co = (float4*)(g_coef + ((size_t)l * N_EDGES + e) * 8);
        co[0] = make_float4(out[0], out[1], out[2], out[3]);
        co[1] = make_float4(out[4], out[5], out[6], out[7]);
    }
}

// ---------------------------------------------------------------------------
// k_v: per-node precompute. Warp = (slot, 32 nodes). Slots:
//   0..4 : v[n,k,:] = h[n,:] @ W2[k]      (-> g_v)
//   5    : v[n,5,:] = h[n,:] @ b2         (-> g_v)
//   6    : agg[n,:] = h[n,:] @ rootW + cb (-> g_agg)
// For layers >0, h is computed inline: BN(prev stats) + leaky on g_agg.
// ---------------------------------------------------------------------------
__global__ void __launch_bounds__(256) k_v(const float* __restrict__ W2,
                                           const float* __restrict__ b2,
                                           const float* __restrict__ rootW,
                                           const float* __restrict__ cb,
                                           const float* __restrict__ bng,
                                           const float* __restrict__ bnb,
                                           int first) {
    __shared__ __align__(16) float sW[7 * C * C];   // 28 KB
    __shared__ float snorm[4 * C];
    __shared__ float scb[C];
    for (int i = threadIdx.x; i < HID * C * C; i += blockDim.x) sW[i] = W2[i];
    for (int i = threadIdx.x; i < C * C; i += blockDim.x) {
        sW[5 * C * C + i] = b2[i];
        sW[6 * C * C + i] = rootW[i];
    }
    if (threadIdx.x < C) {
        scb[threadIdx.x] = cb[threadIdx.x];
        if (!first) {
            float mu = g_stats[threadIdx.x] * (1.0f / N_NODES);
            float var = g_stats[C + threadIdx.x] * (1.0f / N_NODES) - mu * mu;
            snorm[threadIdx.x] = mu;
            snorm[C + threadIdx.x] = rsqrtf(var + BN_EPS);
            snorm[2 * C + threadIdx.x] = bng[threadIdx.x];
            snorm[3 * C + threadIdx.x] = bnb[threadIdx.x];
        }
    }
    __syncthreads();

    int gw = blockIdx.x * 8 + (threadIdx.x >> 5);
    int slot = gw % 7;
    int node = (gw / 7) * 32 + (threadIdx.x & 31);
    if (node >= N_NODES) return;

    float h[C];
    if (first) {
        const float4* hp = (const float4*)(g_h + node * C);
#pragma unroll
        for (int q = 0; q < 8; q++) {
            float4 v = hp[q];
            h[4 * q] = v.x; h[4 * q + 1] = v.y; h[4 * q + 2] = v.z; h[4 * q + 3] = v.w;
        }
    } else {
        const float4* ap = (const float4*)(g_agg + node * C);
#pragma unroll
        for (int q = 0; q < 8; q++) {
            float4 v = ap[q];
            float t[4] = {v.x, v.y, v.z, v.w};
#pragma unroll
            for (int r = 0; r < 4; r++) {
                int c = 4 * q + r;
                float val = (t[r] - snorm[c]) * snorm[C + c] * snorm[2 * C + c] + snorm[3 * C + c];
                h[c] = val > 0.f ? val : 0.01f * val;
            }
        }
    }

    unsigned long long acc[16];
#pragma unroll
    for (int j = 0; j < 16; j++) acc[j] = 0ULL;
    const float* wbase = sW + slot * C * C;
#pragma unroll 8
    for (int c = 0; c < C; c++) {
        unsigned long long p = pack2(h[c]);
        const ulonglong2* wr = (const ulonglong2*)(wbase + c * C);
#pragma unroll
        for (int j = 0; j < 8; j++) {
            ulonglong2 w = wr[j];
            fma2(acc[2 * j], p, w.x);
            fma2(acc[2 * j + 1], p, w.y);
        }
    }

    if (slot == 6) {
        float4* ao = (float4*)(g_agg + node * C);
        const float* af = (const float*)acc;
#pragma unroll
        for (int q = 0; q < 8; q++) {
            float4 v;
            v.x = af[4 * q] + scb[4 * q];
            v.y = af[4 * q + 1] + scb[4 * q + 1];
            v.z = af[4 * q + 2] + scb[4 * q + 2];
            v.w = af[4 * q + 3] + scb[4 * q + 3];
            ao[q] = v;
        }
    } else {
        float4* vo = (float4*)(g_v + node * (6 * C) + slot * C);
        const float4* af = (const float4*)acc;
#pragma unroll
        for (int q = 0; q < 8; q++) vo[q] = af[q];
    }
}

// ---------------------------------------------------------------------------
// Edge kernel, coalesced: 8 lanes per edge (warp = 4 edges).
// Lane owns one float4 slice of the 128B v-row; gather is 4 lines/warp-instr.
// msg = sum_k coef[k]*v[src,k,:], scatter RED.v4 to g_agg[dst].
// Layer index passed as int; coef pointer computed IN DEVICE CODE (the R3/R4
// bug was computing &g_coef[...] on the host -> host shadow address via ATS).
// ---------------------------------------------------------------------------
__global__ void __launch_bounds__(256) k_edge(const int* __restrict__ src,
                                              const int* __restrict__ dst,
                                              int layer) {
    if (blockIdx.x == 0 && threadIdx.x < 2 * C) g_stats[threadIdx.x] = 0.f;

    const float* coefL = g_coef + (size_t)layer * N_EDGES * 8;

    int lane = threadIdx.x & 31;
    int warp = (blockIdx.x * blockDim.x + threadIdx.x) >> 5;
    int group = lane >> 3;   // 0..3: edge within warp
    int d4 = lane & 7;       // float4 slice within 32-float row
    int e = warp * 4 + group;
    if (e >= N_EDGES) return;

    int sn = __ldg(src + e);
    int dn = __ldg(dst + e);
    const float* cp = coefL + e * 8;
    float4 c03 = __ldg((const float4*)cp);
    float2 c45 = __ldg((const float2*)(cp + 4));
    float coef[6] = {c03.x, c03.y, c03.z, c03.w, c45.x, c45.y};

    unsigned long long a0 = 0ULL, a1 = 0ULL;
    const float* vb = g_v + sn * (6 * C) + d4 * 4;
#pragma unroll
    for (int k = 0; k < 6; k++) {
        float ck = coef[k];
        if (ck != 0.f) {
            ulonglong2 w = __ldg((const ulonglong2*)(vb + k * C));
            unsigned long long p = pack2(ck);
            fma2(a0, p, w.x);
            fma2(a1, p, w.y);
        }
    }

    float2 lo = *(float2*)&a0, hi = *(float2*)&a1;
    red_add_v4(g_agg + dn * C + d4 * 4, make_float4(lo.x, lo.y, hi.x, hi.y));
}

// ---------------------------------------------------------------------------
// BN statistics: per-channel sum / sumsq over g_agg.
// ---------------------------------------------------------------------------
__global__ void __launch_bounds__(256) k_stats() {
    __shared__ float ss[2 * C];
    if (threadIdx.x < 2 * C) ss[threadIdx.x] = 0.f;
    __syncthreads();
    const float4* A = (const float4*)g_agg;
    float4 s = {0.f, 0.f, 0.f, 0.f}, q = {0.f, 0.f, 0.f, 0.f};
    int stride = gridDim.x * blockDim.x;
    for (int i = blockIdx.x * blockDim.x + threadIdx.x; i < N_NODES * 8; i += stride) {
        float4 v = A[i];
        s.x += v.x; s.y += v.y; s.z += v.z; s.w += v.w;
        q.x += v.x * v.x; q.y += v.y * v.y; q.z += v.z * v.z; q.w += v.w * v.w;
    }
#pragma unroll
    for (int off = 8; off <= 16; off <<= 1) {
        s.x += __shfl_xor_sync(0xffffffffu, s.x, off);
        s.y += __shfl_xor_sync(0xffffffffu, s.y, off);
        s.z += __shfl_xor_sync(0xffffffffu, s.z, off);
        s.w += __shfl_xor_sync(0xffffffffu, s.w, off);
        q.x += __shfl_xor_sync(0xffffffffu, q.x, off);
        q.y += __shfl_xor_sync(0xffffffffu, q.y, off);
        q.z += __shfl_xor_sync(0xffffffffu, q.z, off);
        q.w += __shfl_xor_sync(0xffffffffu, q.w, off);
    }
    int lane = threadIdx.x & 31;
    if (lane < 8) {
        int cg = lane * 4;
        atomicAdd(&ss[cg + 0], s.x); atomicAdd(&ss[cg + 1], s.y);
        atomicAdd(&ss[cg + 2], s.z); atomicAdd(&ss[cg + 3], s.w);
        atomicAdd(&ss[C + cg + 0], q.x); atomicAdd(&ss[C + cg + 1], q.y);
        atomicAdd(&ss[C + cg + 2], q.z); atomicAdd(&ss[C + cg + 3], q.w);
    }
    __syncthreads();
    if (threadIdx.x < 2 * C) atomicAdd(&g_stats[threadIdx.x], ss[threadIdx.x]);
}

// ---------------------------------------------------------------------------
// Final: BN (no leaky) + prediction dot + scatter to graphs (batch is sorted).
// No early exit: tail lanes clamp node, contribute s=0, and participate in all
// warp collectives.
// ---------------------------------------------------------------------------
__global__ void k_out_init(const float* __restrict__ pb, float* out) {
    int g = blockIdx.x * blockDim.x + threadIdx.x;
    if (g < NG) out[g] = pb[0];
}

__global__ void __launch_bounds__(256) k_fin(const int* __restrict__ batch,
                                             const float* __restrict__ pW,
                                             const float* __restrict__ bng,
                                             const float* __restrict__ bnb,
                                             float* out) {
    __shared__ float snorm[4 * C];
    __shared__ float spw[C];
    if (threadIdx.x < C) {
        float mu = g_stats[threadIdx.x] * (1.0f / N_NODES);
        float var = g_stats[C + threadIdx.x] * (1.0f / N_NODES) - mu * mu;
        snorm[threadIdx.x] = mu;
        snorm[C + threadIdx.x] = rsqrtf(var + BN_EPS);
        snorm[2 * C + threadIdx.x] = bng[threadIdx.x];
        snorm[3 * C + threadIdx.x] = bnb[threadIdx.x];
        spw[threadIdx.x] = pW[threadIdx.x];
    }
    __syncthreads();
    int n = blockIdx.x * blockDim.x + threadIdx.x;
    bool valid = n < N_NODES;
    int nn = valid ? n : N_NODES - 1;
    const float4* ap = (const float4*)(g_agg + nn * C);
    float s = 0.f;
#pragma unroll
    for (int q = 0; q < 8; q++) {
        float4 v = ap[q];
        float t[4] = {v.x, v.y, v.z, v.w};
#pragma unroll
        for (int r = 0; r < 4; r++) {
            int c = 4 * q + r;
            float val = (t[r] - snorm[c]) * snorm[C + c] * snorm[2 * C + c] + snorm[3 * C + c];
            s += val * spw[c];
        }
    }
    if (!valid) s = 0.f;
    int bid = batch[nn];
    int bid0 = __shfl_sync(0xffffffffu, bid, 0);
    bool uni = __all_sync(0xffffffffu, bid == bid0 && valid);
    if (uni) {
#pragma unroll
        for (int off = 16; off >= 1; off >>= 1)
            s += __shfl_xor_sync(0xffffffffu, s, off);
        if ((threadIdx.x & 31) == 0) atomicAdd(&out[bid0], s);
    } else if (valid) {
        atomicAdd(&out[bid], s);
    }
}

// ---------------------------------------------------------------------------
extern "C" void kernel_launch(void* const* d_in, const int* in_sizes, int n_in,
                              void* d_out, int out_size) {
    const float* x       = (const float*)d_in[0];
    const int*   ei      = (const int*)d_in[1];
    const float* ea      = (const float*)d_in[2];
    const int*   batch   = (const int*)d_in[3];
    const float* lin_W   = (const float*)d_in[4];
    const float* lin_b   = (const float*)d_in[5];
    const float* mes_W1  = (const float*)d_in[6];
    const float* mes_b1  = (const float*)d_in[7];
    const float* mes_W2  = (const float*)d_in[8];
    const float* mes_b2  = (const float*)d_in[9];
    const float* root_W  = (const float*)d_in[10];
    const float* conv_b  = (const float*)d_in[11];
    const float* bn_g    = (const float*)d_in[12];
    const float* bn_b    = (const float*)d_in[13];
    const float* pred_W  = (const float*)d_in[14];
    const float* pred_b  = (const float*)d_in[15];
    float* out = (float*)d_out;

    const int* src = ei;
    const int* dst = ei + N_EDGES;

    int vwarps = 7 * ((N_NODES + 31) / 32);
    int vblocks = (vwarps + 7) / 8;
    int eblocks = (N_EDGES / 4 * 32 + 255) / 256;   // 8 lanes/edge

    k_init<<<(N_NODES + 255) / 256, 256>>>(x, lin_W, lin_b);
    k_coef<<<(N_EDGES + 255) / 256, 256>>>(ea, mes_W1, mes_b1);
    for (int l = 0; l < NL; l++) {
        k_v<<<vblocks, 256>>>(mes_W2 + l * HID * C * C, mes_b2 + l * C * C,
                              root_W + l * C * C, conv_b + l * C,
                              l > 0 ? bn_g + (l - 1) * C : bn_g,
                              l > 0 ? bn_b + (l - 1) * C : bn_b,
                              l == 0 ? 1 : 0);
        k_edge<<<eblocks, 256>>>(src, dst, l);
        k_stats<<<1184, 256>>>();
    }
    k_out_init<<<2, 256>>>(pred_b, out);
    k_fin<<<(N_NODES + 255) / 256, 256>>>(batch, pred_W, bn_g + 2 * C, bn_b + 2 * C, out);
}